// round 1
// baseline (speedup 1.0000x reference)
#include <cuda_runtime.h>

// Problem constants (fixed shapes)
#define NU 100000
#define NI 50000
#define NN 150000        // NU + NI
#define D  64
#define DE 16
#define NE 1500000
#define NP 14
#define EPS 1e-5f

// -------- scratch (device globals; no allocation allowed) --------
__device__ float g_y [NN * D];   // layernormed features for current layer
__device__ float g_x0[NN * D];   // layer-1 output
__device__ float g_x1[NN * D];   // layer-2 output
__device__ float g_e0[NE];       // per-edge exp score (attention)
__device__ float g_e1[NE];       // per-edge exp score (path)
__device__ float g_s0[NN];       // row sums for softmax 0
__device__ float g_s1[NN];       // row sums for softmax 1

// ---------------------------------------------------------------
// LayerNorm + prep: one warp per row.
//   y[row]     = LN(src[row])
//   xnext[row] = 0
//   s0/s1[row] = 0
//   outacc[row] = src[row]/3   (first=1)  or  += src[row]/3 (first=0)
// For first layer, src comes from the concatenated user/item embeddings.
// ---------------------------------------------------------------
__global__ void ln_kernel(const float* __restrict__ ue,
                          const float* __restrict__ ie,
                          const float* __restrict__ src,
                          float* __restrict__ y,
                          float* __restrict__ xnext,
                          float* __restrict__ outacc,
                          int first)
{
    int row = blockIdx.x * (blockDim.x >> 5) + (threadIdx.x >> 5);
    if (row >= NN) return;
    int lane = threadIdx.x & 31;

    const float* p;
    if (first)
        p = (row < NU) ? (ue + (size_t)row * D) : (ie + (size_t)(row - NU) * D);
    else
        p = src + (size_t)row * D;

    float2 v = ((const float2*)p)[lane];

    float s = v.x + v.y;
    #pragma unroll
    for (int o = 16; o; o >>= 1) s += __shfl_xor_sync(0xffffffffu, s, o);
    float mu = s * (1.0f / D);

    float dx = v.x - mu, dy = v.y - mu;
    float vs = dx * dx + dy * dy;
    #pragma unroll
    for (int o = 16; o; o >>= 1) vs += __shfl_xor_sync(0xffffffffu, vs, o);
    float inv = rsqrtf(vs * (1.0f / D) + EPS);

    ((float2*)(y + (size_t)row * D))[lane] = make_float2(dx * inv, dy * inv);
    ((float2*)(xnext + (size_t)row * D))[lane] = make_float2(0.f, 0.f);

    float2* op = (float2*)(outacc + (size_t)row * D);
    float2 a = make_float2(v.x * (1.0f / 3.0f), v.y * (1.0f / 3.0f));
    if (first) {
        op[lane] = a;
    } else {
        float2 o = op[lane];
        op[lane] = make_float2(o.x + a.x, o.y + a.y);
    }
    if (lane == 0) { g_s0[row] = 0.f; g_s1[row] = 0.f; }
}

// ---------------------------------------------------------------
// Pass 1: per-edge scores. 8 lanes cooperate on one edge.
//   xs = dot(y[r], y[c]) / sqrt(D);  ys = dot(eigs[r], eigs[c])
//   e0 = min(exp(xs + exp(lam)*ys), 5);  e1 = min(exp(pw[pt]), 5)
//   atomic row sums.
// ---------------------------------------------------------------
__global__ void score_kernel(const float* __restrict__ eigs,
                             const int*   __restrict__ rows,
                             const int*   __restrict__ cols,
                             const int*   __restrict__ pt,
                             const float* __restrict__ lam,   // &lambda0[l]
                             const float* __restrict__ pw)    // &path_w[l*NP]
{
    int t = blockIdx.x * blockDim.x + threadIdx.x;
    int e = t >> 3;
    if (e >= NE) return;
    int sl = t & 7;

    int r = __ldg(rows + e);
    int c = __ldg(cols + e);

    const float4* yr = (const float4*)(g_y + (size_t)r * D);
    const float4* yc = (const float4*)(g_y + (size_t)c * D);

    float4 a = yr[sl],     b = yc[sl];
    float p = a.x*b.x + a.y*b.y + a.z*b.z + a.w*b.w;
    a = yr[sl + 8];        b = yc[sl + 8];
    p += a.x*b.x + a.y*b.y + a.z*b.z + a.w*b.w;
    p *= 0.125f;   // 1/sqrt(64)

    float elam = expf(__ldg(lam));
    if (sl < 4) {
        const float4* er = (const float4*)(eigs + (size_t)r * DE);
        const float4* ec = (const float4*)(eigs + (size_t)c * DE);
        float4 u = er[sl], w = ec[sl];
        p += elam * (u.x*w.x + u.y*w.y + u.z*w.z + u.w*w.w);
    }

    p += __shfl_xor_sync(0xffffffffu, p, 1);
    p += __shfl_xor_sync(0xffffffffu, p, 2);
    p += __shfl_xor_sync(0xffffffffu, p, 4);

    if (sl == 0) {
        float v0 = fminf(expf(p), 5.0f);     // clip(exp, -5, 5) == min since exp>=0
        g_e0[e] = v0;
        atomicAdd(g_s0 + r, v0);
    } else if (sl == 1) {
        float v1 = fminf(expf(__ldg(pw + __ldg(pt + e))), 5.0f);
        g_e1[e] = v1;
        atomicAdd(g_s1 + r, v1);
    }
}

// vector float4 reduction into global memory (sm_90+)
__device__ __forceinline__ void red4(float* addr, float a, float b, float c, float d)
{
    asm volatile("red.global.add.v4.f32 [%0], {%1,%2,%3,%4};"
                 :: "l"(addr), "f"(a), "f"(b), "f"(c), "f"(d) : "memory");
}

// ---------------------------------------------------------------
// Pass 2: SpMM. 8 lanes per edge; s = 0.5*(e0/d0 + e1/d1); xn[r] += s*y[c]
// ---------------------------------------------------------------
__global__ void spmm_kernel(const int* __restrict__ rows,
                            const int* __restrict__ cols,
                            float* __restrict__ xn)
{
    int t = blockIdx.x * blockDim.x + threadIdx.x;
    int e = t >> 3;
    if (e >= NE) return;
    int sl = t & 7;

    int r = __ldg(rows + e);
    int c = __ldg(cols + e);

    float d0 = __ldg(g_s0 + r); d0 = (d0 == 0.f) ? 1.f : d0;
    float d1 = __ldg(g_s1 + r); d1 = (d1 == 0.f) ? 1.f : d1;
    float s = 0.5f * (__ldg(g_e0 + e) / d0 + __ldg(g_e1 + e) / d1);

    const float4* yc = (const float4*)(g_y + (size_t)c * D);
    float* xr = xn + (size_t)r * D;

    float4 v = yc[sl];
    red4(xr + sl * 4,       s * v.x, s * v.y, s * v.z, s * v.w);
    v = yc[sl + 8];
    red4(xr + (sl + 8) * 4, s * v.x, s * v.y, s * v.z, s * v.w);
}

// out += x_last / 3
__global__ void final_kernel(const float* __restrict__ xl, float* __restrict__ out)
{
    int i = blockIdx.x * blockDim.x + threadIdx.x;
    if (i >= NN * D / 4) return;
    float4 v = ((const float4*)xl)[i];
    float4 o = ((float4*)out)[i];
    o.x += v.x * (1.0f / 3.0f);
    o.y += v.y * (1.0f / 3.0f);
    o.z += v.z * (1.0f / 3.0f);
    o.w += v.w * (1.0f / 3.0f);
    ((float4*)out)[i] = o;
}

extern "C" void kernel_launch(void* const* d_in, const int* in_sizes, int n_in,
                              void* d_out, int out_size)
{
    const float* ue    = (const float*)d_in[0];  // [NU, D]
    const float* ie    = (const float*)d_in[1];  // [NI, D]
    const float* eigs  = (const float*)d_in[2];  // [NN, DE]
    const float* lam   = (const float*)d_in[3];  // [2]
    const float* pw    = (const float*)d_in[4];  // [2, NP]
    const int*   idx   = (const int*)  d_in[5];  // [2, 2, NE]
    const int*   pt    = (const int*)  d_in[6];  // [2, NE]
    float* out = (float*)d_out;

    float* y  = nullptr; float* x0 = nullptr; float* x1 = nullptr;
    cudaGetSymbolAddress((void**)&y,  g_y);
    cudaGetSymbolAddress((void**)&x0, g_x0);
    cudaGetSymbolAddress((void**)&x1, g_x1);

    dim3 lnGrid((NN + 7) / 8);
    dim3 lnBlk(256);
    int edgeBlocks = (NE * 8 + 255) / 256;

    // ---- layer 1: src = concat(ue, ie) ----
    ln_kernel<<<lnGrid, lnBlk>>>(ue, ie, nullptr, y, x0, out, 1);
    score_kernel<<<edgeBlocks, 256>>>(eigs, idx, idx + NE, pt, lam, pw);
    spmm_kernel<<<edgeBlocks, 256>>>(idx, idx + NE, x0);

    // ---- layer 2: src = x0 ----
    ln_kernel<<<lnGrid, lnBlk>>>(nullptr, nullptr, x0, y, x1, out, 0);
    score_kernel<<<edgeBlocks, 256>>>(eigs, idx + 2 * NE, idx + 3 * NE,
                                      pt + NE, lam + 1, pw + NP);
    spmm_kernel<<<edgeBlocks, 256>>>(idx + 2 * NE, idx + 3 * NE, x1);

    // ---- final: out += x1/3 ----
    final_kernel<<<(NN * D / 4 + 255) / 256, 256>>>(x1, out);
}

// round 2
// speedup vs baseline: 1.2130x; 1.2130x over previous
#include <cuda_runtime.h>
#include <cuda_fp16.h>

// Problem constants (fixed shapes)
#define NU 100000
#define NI 50000
#define NN 150000        // NU + NI
#define D  64
#define DE 16
#define NE 1500000
#define NP 14
#define EPS 1e-5f

#define SCAN_BLK 1024
#define NB ((NN + SCAN_BLK - 1) / SCAN_BLK)   // 147 scan blocks

// -------- scratch (device globals; no allocation allowed) --------
__device__ float  g_y  [NN * D];   // layernormed features, fp32 (SpMM values)
__device__ __half g_yh [NN * D];   // layernormed features, fp16 (score dots)
__device__ float  g_x0 [NN * D];   // layer-1 output
__device__ float  g_x1 [NN * D];   // layer-2 output
__device__ int    g_cnt[NN];       // row degree
__device__ int    g_rs [NN];       // CSR row start (exclusive scan of cnt)
__device__ int    g_cur[NN];       // scatter cursor (copy of row start)
__device__ float  g_s0 [NN];       // softmax-0 row sums
__device__ float  g_s1 [NN];       // softmax-1 row sums
__device__ int    g_csr_c [NE];    // CSR: column index
__device__ float  g_csr_e0[NE];    // CSR: exp score 0
__device__ float  g_csr_e1[NE];    // CSR: exp score 1
__device__ int    g_part[256];     // scan partials

// ---------------------------------------------------------------
// LayerNorm + per-layer init: one warp per row.
//   y / yh [row] = LN(src[row]);  cnt/s0/s1[row] = 0
// ---------------------------------------------------------------
__global__ void ln_kernel(const float* __restrict__ ue,
                          const float* __restrict__ ie,
                          const float* __restrict__ src,
                          int first)
{
    int row = blockIdx.x * (blockDim.x >> 5) + (threadIdx.x >> 5);
    if (row >= NN) return;
    int lane = threadIdx.x & 31;

    const float* p;
    if (first)
        p = (row < NU) ? (ue + (size_t)row * D) : (ie + (size_t)(row - NU) * D);
    else
        p = src + (size_t)row * D;

    float2 v = ((const float2*)p)[lane];

    float s = v.x + v.y;
    #pragma unroll
    for (int o = 16; o; o >>= 1) s += __shfl_xor_sync(0xffffffffu, s, o);
    float mu = s * (1.0f / D);

    float dx = v.x - mu, dy = v.y - mu;
    float vs = dx * dx + dy * dy;
    #pragma unroll
    for (int o = 16; o; o >>= 1) vs += __shfl_xor_sync(0xffffffffu, vs, o);
    float inv = rsqrtf(vs * (1.0f / D) + EPS);

    float nx = dx * inv, ny = dy * inv;
    ((float2*)(g_y + (size_t)row * D))[lane] = make_float2(nx, ny);
    ((__half2*)(g_yh + (size_t)row * D))[lane] = __floats2half2_rn(nx, ny);

    if (lane == 0) { g_cnt[row] = 0; g_s0[row] = 0.f; g_s1[row] = 0.f; }
}

// ---------------- CSR build: histogram + scan ----------------
__global__ void hist_kernel(const int* __restrict__ rows)
{
    int e = blockIdx.x * blockDim.x + threadIdx.x;
    if (e < NE) atomicAdd(&g_cnt[__ldg(rows + e)], 1);
}

__global__ void scan1_kernel()
{
    __shared__ int sh[SCAN_BLK];
    int i = blockIdx.x * SCAN_BLK + threadIdx.x;
    int v = (i < NN) ? g_cnt[i] : 0;
    sh[threadIdx.x] = v;
    __syncthreads();
    #pragma unroll
    for (int o = 1; o < SCAN_BLK; o <<= 1) {
        int t = (threadIdx.x >= o) ? sh[threadIdx.x - o] : 0;
        __syncthreads();
        sh[threadIdx.x] += t;
        __syncthreads();
    }
    if (i < NN) g_rs[i] = sh[threadIdx.x] - v;            // exclusive
    if (threadIdx.x == SCAN_BLK - 1) g_part[blockIdx.x] = sh[SCAN_BLK - 1];
}

__global__ void scan2_kernel()
{
    __shared__ int sh[256];
    int t = threadIdx.x;
    int v = (t < NB) ? g_part[t] : 0;
    sh[t] = v;
    __syncthreads();
    #pragma unroll
    for (int o = 1; o < 256; o <<= 1) {
        int x = (t >= o) ? sh[t - o] : 0;
        __syncthreads();
        sh[t] += x;
        __syncthreads();
    }
    if (t < NB) g_part[t] = sh[t] - v;                    // exclusive
}

__global__ void scan3_kernel()
{
    int i = blockIdx.x * blockDim.x + threadIdx.x;
    if (i >= NN) return;
    int v = g_rs[i] + g_part[i >> 10];
    g_rs[i]  = v;
    g_cur[i] = v;
}

// ---------------------------------------------------------------
// Pass 1: per-edge scores + CSR scatter. 4 lanes per edge.
//   xs = dot(yh[r], yh[c]) / 8;  ys = dot(eigs[r], eigs[c]) [fp32]
//   e0 = min(exp(xs + exp(lam)*ys), 5);  e1 = min(exp(pw[pt]), 5)
// ---------------------------------------------------------------
__global__ void score_kernel(const float* __restrict__ eigs,
                             const int*   __restrict__ rows,
                             const int*   __restrict__ cols,
                             const int*   __restrict__ pt,
                             const float* __restrict__ lam,
                             const float* __restrict__ pw)
{
    int t = blockIdx.x * blockDim.x + threadIdx.x;
    int e = t >> 2;
    if (e >= NE) return;
    int sl = t & 3;

    int r = __ldg(rows + e);
    int c = __ldg(cols + e);

    const float4* hr = (const float4*)(g_yh + (size_t)r * D);
    const float4* hc = (const float4*)(g_yh + (size_t)c * D);

    float dp = 0.f;
    #pragma unroll
    for (int k = 0; k < 2; k++) {
        float4 a = hr[sl + 4 * k];
        float4 b = hc[sl + 4 * k];
        const __half2* ah = (const __half2*)&a;
        const __half2* bh = (const __half2*)&b;
        #pragma unroll
        for (int j = 0; j < 4; j++) {
            float2 af = __half22float2(ah[j]);
            float2 bf = __half22float2(bh[j]);
            dp += af.x * bf.x + af.y * bf.y;
        }
    }

    float4 u = ((const float4*)(eigs + (size_t)r * DE))[sl];
    float4 w = ((const float4*)(eigs + (size_t)c * DE))[sl];
    float ys = u.x * w.x + u.y * w.y + u.z * w.z + u.w * w.w;

    float elam = expf(__ldg(lam));
    float p = dp * 0.125f + elam * ys;
    p += __shfl_xor_sync(0xffffffffu, p, 1);
    p += __shfl_xor_sync(0xffffffffu, p, 2);

    if (sl == 0) {
        float v0 = fminf(expf(p), 5.0f);                          // clip(exp,-5,5)
        float v1 = fminf(expf(__ldg(pw + __ldg(pt + e))), 5.0f);
        int pos = atomicAdd(&g_cur[r], 1);
        g_csr_c [pos] = c;
        g_csr_e0[pos] = v0;
        g_csr_e1[pos] = v1;
        atomicAdd(&g_s0[r], v0);
        atomicAdd(&g_s1[r], v1);
    }
}

// ---------------------------------------------------------------
// Pass 2: SpMM via CSR. One warp per row; register accumulation.
// ---------------------------------------------------------------
__global__ void spmm_kernel(float* __restrict__ xn)
{
    int row = blockIdx.x * (blockDim.x >> 5) + (threadIdx.x >> 5);
    if (row >= NN) return;
    int lane = threadIdx.x & 31;

    int n  = g_cnt[row];
    int st = g_rs[row];
    float d0 = g_s0[row]; d0 = (d0 == 0.f) ? 1.f : d0;
    float d1 = g_s1[row]; d1 = (d1 == 0.f) ? 1.f : d1;
    float id0 = 0.5f / d0, id1 = 0.5f / d1;

    float ax = 0.f, ay = 0.f;
    for (int i = 0; i < n; i++) {
        int slot = st + i;
        int cc   = __ldg(&g_csr_c[slot]);
        float s  = __ldg(&g_csr_e0[slot]) * id0 + __ldg(&g_csr_e1[slot]) * id1;
        float2 v = ((const float2*)(g_y + (size_t)cc * D))[lane];
        ax += s * v.x;
        ay += s * v.y;
    }
    ((float2*)(xn + (size_t)row * D))[lane] = make_float2(ax, ay);
}

// ---------------- out = (concat(ue,ie) + x0 + x1) / 3 ----------------
__global__ void final_kernel(const float* __restrict__ ue,
                             const float* __restrict__ ie,
                             float* __restrict__ out)
{
    int i = blockIdx.x * blockDim.x + threadIdx.x;        // float4 index
    if (i >= NN * D / 4) return;
    int row = i >> 4;                                     // D/4 = 16 float4/row
    int k   = i & 15;

    float4 a = (row < NU)
        ? ((const float4*)(ue + (size_t)row * D))[k]
        : ((const float4*)(ie + (size_t)(row - NU) * D))[k];
    float4 b = ((const float4*)g_x0)[i];
    float4 c = ((const float4*)g_x1)[i];

    float4 o;
    o.x = (a.x + b.x + c.x) * (1.0f / 3.0f);
    o.y = (a.y + b.y + c.y) * (1.0f / 3.0f);
    o.z = (a.z + b.z + c.z) * (1.0f / 3.0f);
    o.w = (a.w + b.w + c.w) * (1.0f / 3.0f);
    ((float4*)out)[i] = o;
}

extern "C" void kernel_launch(void* const* d_in, const int* in_sizes, int n_in,
                              void* d_out, int out_size)
{
    const float* ue   = (const float*)d_in[0];  // [NU, D]
    const float* ie   = (const float*)d_in[1];  // [NI, D]
    const float* eigs = (const float*)d_in[2];  // [NN, DE]
    const float* lam  = (const float*)d_in[3];  // [2]
    const float* pw   = (const float*)d_in[4];  // [2, NP]
    const int*   idx  = (const int*)  d_in[5];  // [2, 2, NE]
    const int*   pt   = (const int*)  d_in[6];  // [2, NE]
    float* out = (float*)d_out;

    float* x0 = nullptr; float* x1 = nullptr;
    cudaGetSymbolAddress((void**)&x0, g_x0);
    cudaGetSymbolAddress((void**)&x1, g_x1);

    dim3 rowGrid((NN + 7) / 8);            // 8 warps/block, warp per row
    int edgeBlocks4 = (NE * 4 + 255) / 256;
    int histBlocks  = (NE + 255) / 256;

    for (int l = 0; l < 2; l++) {
        const int* rows = idx + (size_t)l * 2 * NE;
        const int* cols = rows + NE;
        float* xn = (l == 0) ? x0 : x1;
        const float* src = (l == 0) ? nullptr : x0;

        ln_kernel<<<rowGrid, 256>>>(ue, ie, src, l == 0);
        hist_kernel<<<histBlocks, 256>>>(rows);
        scan1_kernel<<<NB, SCAN_BLK>>>();
        scan2_kernel<<<1, 256>>>();
        scan3_kernel<<<(NN + 255) / 256, 256>>>();
        score_kernel<<<edgeBlocks4, 256>>>(eigs, rows, cols, pt + (size_t)l * NE,
                                           lam + l, pw + (size_t)l * NP);
        spmm_kernel<<<rowGrid, 256>>>(xn);
    }

    final_kernel<<<(NN * D / 4 + 255) / 256, 256>>>(ue, ie, out);
}

// round 4
// speedup vs baseline: 1.4037x; 1.1572x over previous
#include <cuda_runtime.h>
#include <cuda_fp16.h>

// Problem constants (fixed shapes)
#define NU 100000
#define NI 50000
#define NN 150000        // NU + NI
#define D  64
#define DE 16
#define NE 1500000
#define NP 14
#define EPS 1e-5f

#define SCAN_BLK 1024
#define NB ((NN + SCAN_BLK - 1) / SCAN_BLK)   // 147 scan blocks
#define ROWB ((NN + 7) / 8)                   // 18750 LN blocks (8 warps each)
#define HISTB ((NE / 4 + 255) / 256)          // 1465 hist blocks (4 edges/thread)

// -------- scratch (device globals; no allocation allowed) --------
__device__ __half g_yh [NN * D];   // layernormed features, fp16
__device__ float  g_x0 [NN * D];   // layer-1 output
__device__ float  g_x1 [NN * D];   // layer-2 output
__device__ int    g_cnt[NN];       // row degree
__device__ int    g_rs [NN];       // CSR row start
__device__ int    g_cur[NN];       // scatter cursor
__device__ float  g_s0 [NN];       // softmax-0 row sums
__device__ float  g_s1 [NN];       // softmax-1 row sums
__device__ int    g_csr_c[NE];     // CSR: column index
__device__ float2 g_csr_e[NE];     // CSR: (e0, e1)
__device__ int    g_part[SCAN_BLK];// scan partials (NB <= 1024)
__device__ int    g_scan_ctr;      // scan completion counter

// ---------------------------------------------------------------
// Fused LayerNorm + histogram.
//   blocks [0, ROWB)         : warp-per-row LN -> fp16, zero s0/s1
//   blocks [ROWB, ROWB+HISTB): histogram of rows[] into g_cnt
// g_cnt is zeroed by zero_cnt_kernel BEFORE this kernel (no in-kernel
// zeroing of g_cnt here — that raced with the hist atomics in R3).
// ---------------------------------------------------------------
__global__ void ln_hist_kernel(const float* __restrict__ ue,
                               const float* __restrict__ ie,
                               const float* __restrict__ src,
                               const int*   __restrict__ rows,
                               int first)
{
    if (blockIdx.x < ROWB) {
        int row = blockIdx.x * 8 + (threadIdx.x >> 5);
        if (row >= NN) return;
        int lane = threadIdx.x & 31;

        const float* p;
        if (first)
            p = (row < NU) ? (ue + (size_t)row * D) : (ie + (size_t)(row - NU) * D);
        else
            p = src + (size_t)row * D;

        float2 v = ((const float2*)p)[lane];

        float s = v.x + v.y;
        #pragma unroll
        for (int o = 16; o; o >>= 1) s += __shfl_xor_sync(0xffffffffu, s, o);
        float mu = s * (1.0f / D);

        float dx = v.x - mu, dy = v.y - mu;
        float vs = dx * dx + dy * dy;
        #pragma unroll
        for (int o = 16; o; o >>= 1) vs += __shfl_xor_sync(0xffffffffu, vs, o);
        float inv = rsqrtf(vs * (1.0f / D) + EPS);

        ((__half2*)(g_yh + (size_t)row * D))[lane] =
            __floats2half2_rn(dx * inv, dy * inv);

        // s0/s1 are only touched by score_kernel (a later launch) -> safe.
        if (lane == 0) { g_s0[row] = 0.f; g_s1[row] = 0.f; }
    } else {
        int e4 = (blockIdx.x - ROWB) * blockDim.x + threadIdx.x;
        if (e4 < NE / 4) {
            int4 r4 = ((const int4*)rows)[e4];
            atomicAdd(&g_cnt[r4.x], 1);
            atomicAdd(&g_cnt[r4.y], 1);
            atomicAdd(&g_cnt[r4.z], 1);
            atomicAdd(&g_cnt[r4.w], 1);
        }
    }
}

// zero cnt + reset scan counter (runs before ln_hist each layer)
__global__ void zero_cnt_kernel()
{
    int i = blockIdx.x * blockDim.x + threadIdx.x;
    if (i == 0) g_scan_ctr = 0;
    if (i < NN / 4) ((int4*)g_cnt)[i] = make_int4(0, 0, 0, 0);
    // NN = 150000 divisible by 4
}

// ---------------------------------------------------------------
// Scan: one kernel. Each block scans 1024 counts; last block to finish
// scans the NB block partials. scan3 applies offsets.
// ---------------------------------------------------------------
__device__ __forceinline__ int warp_incl_scan(int x, int lane)
{
    #pragma unroll
    for (int o = 1; o < 32; o <<= 1) {
        int t = __shfl_up_sync(0xffffffffu, x, o);
        if (lane >= o) x += t;
    }
    return x;
}

__global__ void scan_kernel()
{
    __shared__ int warpsum[32];
    __shared__ int s_total;
    __shared__ int s_isLast;

    int lane = threadIdx.x & 31;
    int wid  = threadIdx.x >> 5;
    int i = blockIdx.x * SCAN_BLK + threadIdx.x;
    int v = (i < NN) ? g_cnt[i] : 0;

    int inc = warp_incl_scan(v, lane);
    if (lane == 31) warpsum[wid] = inc;
    __syncthreads();
    if (wid == 0) {
        int s  = warpsum[lane];
        int si = warp_incl_scan(s, lane);
        warpsum[lane] = si - s;              // exclusive warp offsets
        if (lane == 31) s_total = si;
    }
    __syncthreads();
    int excl = inc - v + warpsum[wid];
    if (i < NN) g_rs[i] = excl;

    if (threadIdx.x == 0) {
        g_part[blockIdx.x] = s_total;
        __threadfence();
        s_isLast = (atomicAdd(&g_scan_ctr, 1) == (int)gridDim.x - 1);
    }
    __syncthreads();

    if (s_isLast) {
        int pv = (threadIdx.x < NB) ? g_part[threadIdx.x] : 0;
        int inc2 = warp_incl_scan(pv, lane);
        __syncthreads();                     // warpsum reuse
        if (lane == 31) warpsum[wid] = inc2;
        __syncthreads();
        if (wid == 0) {
            int s  = warpsum[lane];
            int si = warp_incl_scan(s, lane);
            warpsum[lane] = si - s;
        }
        __syncthreads();
        int excl2 = inc2 - pv + warpsum[wid];
        if (threadIdx.x < NB) g_part[threadIdx.x] = excl2;
    }
}

__global__ void scan3_kernel()
{
    int i = blockIdx.x * blockDim.x + threadIdx.x;
    if (i >= NN) return;
    int v = g_rs[i] + g_part[i >> 10];
    g_rs[i]  = v;
    g_cur[i] = v;
}

// ---------------------------------------------------------------
// Pass 1: per-edge scores + CSR scatter. 4 lanes per edge.
// ---------------------------------------------------------------
__global__ void score_kernel(const float* __restrict__ eigs,
                             const int*   __restrict__ rows,
                             const int*   __restrict__ cols,
                             const int*   __restrict__ pt,
                             const float* __restrict__ lam,
                             const float* __restrict__ pw)
{
    int t = blockIdx.x * blockDim.x + threadIdx.x;
    int e = t >> 2;
    if (e >= NE) return;
    int sl = t & 3;

    int r = __ldg(rows + e);
    int c = __ldg(cols + e);

    const float4* hr = (const float4*)(g_yh + (size_t)r * D);
    const float4* hc = (const float4*)(g_yh + (size_t)c * D);

    float dp = 0.f;
    #pragma unroll
    for (int k = 0; k < 2; k++) {
        float4 a = hr[sl + 4 * k];
        float4 b = hc[sl + 4 * k];
        const __half2* ah = (const __half2*)&a;
        const __half2* bh = (const __half2*)&b;
        #pragma unroll
        for (int j = 0; j < 4; j++) {
            float2 af = __half22float2(ah[j]);
            float2 bf = __half22float2(bh[j]);
            dp += af.x * bf.x + af.y * bf.y;
        }
    }

    float4 u = ((const float4*)(eigs + (size_t)r * DE))[sl];
    float4 w = ((const float4*)(eigs + (size_t)c * DE))[sl];
    float ys = u.x * w.x + u.y * w.y + u.z * w.z + u.w * w.w;

    float elam = expf(__ldg(lam));
    float p = dp * 0.125f + elam * ys;
    p += __shfl_xor_sync(0xffffffffu, p, 1);
    p += __shfl_xor_sync(0xffffffffu, p, 2);

    if (sl == 0) {
        float v0 = fminf(expf(p), 5.0f);                          // clip(exp,-5,5)
        float v1 = fminf(expf(__ldg(pw + __ldg(pt + e))), 5.0f);
        int pos = atomicAdd(&g_cur[r], 1);
        g_csr_c[pos] = c;
        g_csr_e[pos] = make_float2(v0, v1);
        atomicAdd(&g_s0[r], v0);
        atomicAdd(&g_s1[r], v1);
    }
}

// ---------------------------------------------------------------
// Pass 2: SpMM via CSR, fp16 value gather. One warp per row.
// ---------------------------------------------------------------
__global__ void spmm_kernel(float* __restrict__ xn)
{
    int row = blockIdx.x * (blockDim.x >> 5) + (threadIdx.x >> 5);
    if (row >= NN) return;
    int lane = threadIdx.x & 31;

    int n  = g_cnt[row];
    int st = g_rs[row];
    float d0 = g_s0[row]; d0 = (d0 == 0.f) ? 1.f : d0;
    float d1 = g_s1[row]; d1 = (d1 == 0.f) ? 1.f : d1;
    float id0 = 0.5f / d0, id1 = 0.5f / d1;

    float ax = 0.f, ay = 0.f;
    for (int i = 0; i < n; i++) {
        int slot = st + i;
        int cc    = __ldg(&g_csr_c[slot]);
        float2 ee = __ldg(&g_csr_e[slot]);
        float s   = ee.x * id0 + ee.y * id1;
        __half2 h = ((const __half2*)(g_yh + (size_t)cc * D))[lane];
        float2 v  = __half22float2(h);
        ax += s * v.x;
        ay += s * v.y;
    }
    ((float2*)(xn + (size_t)row * D))[lane] = make_float2(ax, ay);
}

// ---------------- out = (concat(ue,ie) + x0 + x1) / 3 ----------------
__global__ void final_kernel(const float* __restrict__ ue,
                             const float* __restrict__ ie,
                             float* __restrict__ out)
{
    int i = blockIdx.x * blockDim.x + threadIdx.x;        // float4 index
    if (i >= NN * D / 4) return;
    int row = i >> 4;                                     // D/4 = 16 float4/row
    int k   = i & 15;

    float4 a = (row < NU)
        ? ((const float4*)(ue + (size_t)row * D))[k]
        : ((const float4*)(ie + (size_t)(row - NU) * D))[k];
    float4 b = ((const float4*)g_x0)[i];
    float4 c = ((const float4*)g_x1)[i];

    float4 o;
    o.x = (a.x + b.x + c.x) * (1.0f / 3.0f);
    o.y = (a.y + b.y + c.y) * (1.0f / 3.0f);
    o.z = (a.z + b.z + c.z) * (1.0f / 3.0f);
    o.w = (a.w + b.w + c.w) * (1.0f / 3.0f);
    ((float4*)out)[i] = o;
}

extern "C" void kernel_launch(void* const* d_in, const int* in_sizes, int n_in,
                              void* d_out, int out_size)
{
    const float* ue   = (const float*)d_in[0];  // [NU, D]
    const float* ie   = (const float*)d_in[1];  // [NI, D]
    const float* eigs = (const float*)d_in[2];  // [NN, DE]
    const float* lam  = (const float*)d_in[3];  // [2]
    const float* pw   = (const float*)d_in[4];  // [2, NP]
    const int*   idx  = (const int*)  d_in[5];  // [2, 2, NE]
    const int*   pt   = (const int*)  d_in[6];  // [2, NE]
    float* out = (float*)d_out;

    float* x0 = nullptr; float* x1 = nullptr;
    cudaGetSymbolAddress((void**)&x0, g_x0);
    cudaGetSymbolAddress((void**)&x1, g_x1);

    dim3 rowGrid(ROWB);                    // 8 warps/block, warp per row
    int edgeBlocks4 = (NE * 4 + 255) / 256;

    for (int l = 0; l < 2; l++) {
        const int* rows = idx + (size_t)l * 2 * NE;
        const int* cols = rows + NE;
        float* xn = (l == 0) ? x0 : x1;
        const float* src = (l == 0) ? nullptr : x0;

        zero_cnt_kernel<<<(NN / 4 + 255) / 256, 256>>>();
        ln_hist_kernel<<<ROWB + HISTB, 256>>>(ue, ie, src, rows, l == 0);
        scan_kernel<<<NB, SCAN_BLK>>>();
        scan3_kernel<<<(NN + 255) / 256, 256>>>();
        score_kernel<<<edgeBlocks4, 256>>>(eigs, rows, cols, pt + (size_t)l * NE,
                                           lam + l, pw + (size_t)l * NP);
        spmm_kernel<<<rowGrid, 256>>>(xn);
    }

    final_kernel<<<(NN * D / 4 + 255) / 256, 256>>>(ue, ie, out);
}